// round 3
// baseline (speedup 1.0000x reference)
#include <cuda_runtime.h>
#include <cstddef>

// SparseConv2D: 3x3 conv (Cin=32 -> Cout=32) on 16x16 patches at stride 14,
// keep 14x14 interior, gate each block by max(mask block) > 0.5.
// Shapes: x (8,506,506,32) f32, mask (8,506,506,1) f32, kernel (3,3,32,32) f32,
// bias (32) f32, out (8,504,504,32) f32.

#define BSZ   16
#define STR   14
#define CIN   32
#define COUT  32
#define NBH   36
#define NBW   36
#define HIN   506
#define WIN   506
#define HOUT  504
#define WOUT  504

struct SmemLayout {
    float patch[BSZ][BSZ][CIN];      // 32 KB  [r][c][cin]
    float wgt[3][3][CIN][COUT];      // 36 KB  [ky][kx][cin][cout]
    float red[8];
    float scale;
};

__global__ __launch_bounds__(224, 3)
void sparse_conv3x3_kernel(const float* __restrict__ x,
                           const float* __restrict__ mask,
                           const float* __restrict__ wglob,
                           const float* __restrict__ bias,
                           float* __restrict__ out)
{
    extern __shared__ char smem_raw[];
    SmemLayout* sm = reinterpret_cast<SmemLayout*>(smem_raw);

    const int bw = blockIdx.x;          // block col 0..35
    const int bh = blockIdx.y;          // block row 0..35
    const int n  = blockIdx.z;          // batch 0..7
    const int tx = threadIdx.x;         // cout lane 0..31
    const int ty = threadIdx.y;         // row-pair 0..6
    const int tid = ty * 32 + tx;       // 0..223

    const int r0 = bh * STR;            // input/patch row base
    const int c0 = bw * STR;            // input/patch col base

    // ---- load weights (9216 floats = 2304 float4) ----
    {
        const float4* w4  = reinterpret_cast<const float4*>(wglob);
        float4*       sw4 = reinterpret_cast<float4*>(&sm->wgt[0][0][0][0]);
        #pragma unroll 1
        for (int i = tid; i < (3 * 3 * CIN * COUT) / 4; i += 224)
            sw4[i] = w4[i];
    }

    // ---- load 16x16x32 patch (2048 float4) ----
    {
        float4* sp4 = reinterpret_cast<float4*>(&sm->patch[0][0][0]);
        #pragma unroll 1
        for (int e = tid; e < 2048; e += 224) {
            int cin4 = e & 7;            // float4 group within cin
            int c    = (e >> 3) & 15;
            int r    = e >> 7;
            const float4* src = reinterpret_cast<const float4*>(
                x + (((size_t)n * HIN + (r0 + r)) * WIN + (c0 + c)) * CIN) + cin4;
            sp4[e] = *src;
        }
    }

    // ---- block-active mask: max over 16x16 mask patch ----
    {
        float m;
        {
            int r = tid >> 4, c = tid & 15;
            m = mask[((size_t)n * HIN + (r0 + r)) * WIN + (c0 + c)];
            if (tid < 32) {
                int j = tid + 224;
                int r2 = j >> 4, c2 = j & 15;
                m = fmaxf(m, mask[((size_t)n * HIN + (r0 + r2)) * WIN + (c0 + c2)]);
            }
        }
        #pragma unroll
        for (int off = 16; off; off >>= 1)
            m = fmaxf(m, __shfl_xor_sync(0xffffffffu, m, off));
        if (tx == 0) sm->red[ty] = m;     // warp == fixed ty (blockDim.x == 32)
    }
    __syncthreads();
    if (tid == 0) {
        float mm = sm->red[0];
        #pragma unroll
        for (int i = 1; i < 7; i++) mm = fmaxf(mm, sm->red[i]);
        sm->scale = (mm > 0.5f) ? 1.0f : 0.0f;
    }
    __syncthreads();

    // ---- compute: each thread owns 2 adjacent output rows (2*ty, 2*ty+1),
    //      14 cols each, for cout = tx. Tap rows rbase..rbase+3 are loaded
    //      once per cin and reused across both output rows. ----
    float acc0[14], acc1[14];
    #pragma unroll
    for (int i = 0; i < 14; i++) { acc0[i] = 0.0f; acc1[i] = 0.0f; }

    const int rbase = 2 * ty;           // output row pair base (0..12)

    #pragma unroll 1
    for (int cin = 0; cin < CIN; ++cin) {
        #pragma unroll
        for (int kr = 0; kr < 4; ++kr) {
            float xv[16];
            #pragma unroll
            for (int c = 0; c < 16; c++)
                xv[c] = sm->patch[rbase + kr][c][cin];

            // output row rbase uses patch tap rows rbase+0..2  (ky = kr)
            if (kr < 3) {
                #pragma unroll
                for (int kx = 0; kx < 3; kx++) {
                    float w = sm->wgt[kr][kx][cin][tx];
                    #pragma unroll
                    for (int c = 0; c < 14; c++)
                        acc0[c] = fmaf(xv[c + kx], w, acc0[c]);
                }
            }
            // output row rbase+1 uses patch tap rows rbase+1..3 (ky = kr-1)
            if (kr >= 1) {
                #pragma unroll
                for (int kx = 0; kx < 3; kx++) {
                    float w = sm->wgt[kr - 1][kx][cin][tx];
                    #pragma unroll
                    for (int c = 0; c < 14; c++)
                        acc1[c] = fmaf(xv[c + kx], w, acc1[c]);
                }
            }
        }
    }

    // ---- epilogue: (conv + bias) * active ----
    const float sc = sm->scale;
    const float b  = bias[tx];
    const int orow = bh * STR + rbase;
    const int ocol = bw * STR;
    size_t obase = (((size_t)n * HOUT + orow) * WOUT + ocol) * COUT + tx;
    #pragma unroll
    for (int c = 0; c < 14; c++) {
        out[obase + (size_t)c * COUT]                        = (acc0[c] + b) * sc;
        out[obase + (size_t)WOUT * COUT + (size_t)c * COUT]  = (acc1[c] + b) * sc;
    }
}

extern "C" void kernel_launch(void* const* d_in, const int* in_sizes, int n_in,
                              void* d_out, int out_size)
{
    const float* x    = (const float*)d_in[0];
    const float* mask = (const float*)d_in[1];
    const float* w    = (const float*)d_in[2];
    const float* bias = (const float*)d_in[3];
    float* out        = (float*)d_out;

    (void)in_sizes; (void)n_in; (void)out_size;

    cudaFuncSetAttribute(sparse_conv3x3_kernel,
                         cudaFuncAttributeMaxDynamicSharedMemorySize,
                         (int)sizeof(SmemLayout));

    dim3 grid(NBW, NBH, 8);
    dim3 block(32, 7);
    sparse_conv3x3_kernel<<<grid, block, sizeof(SmemLayout)>>>(x, mask, w, bias, out);
}